// round 3
// baseline (speedup 1.0000x reference)
#include <cuda_runtime.h>
#include <cuda_bf16.h>
#include <cstdint>

#define MAX_NODES 100000
#define HID 64
#define N_GRAPHS 64
#define OUT_CH 2

// Scratch (no cudaMalloc allowed)
__device__ float g_h[MAX_NODES * HID];      // 25.6 MB
__device__ float g_agg[MAX_NODES * HID];    // 25.6 MB
__device__ float g_dinv[MAX_NODES];
__device__ float g_pooled[N_GRAPHS * HID];
__device__ float g_cnt[N_GRAPHS];

// ---------------------------------------------------------------------------
// degree
// ---------------------------------------------------------------------------
__global__ void k_deg_init(float* deg, int n) {
    int i = blockIdx.x * blockDim.x + threadIdx.x;
    if (i < n) deg[i] = 1.0f;
}

__global__ void k_deg_scatter(const int* __restrict__ ei, int E, float* deg) {
    int e = blockIdx.x * blockDim.x + threadIdx.x;
    if (e < E) {
        int c = ei[E + e];          // col = second row of edge_index
        atomicAdd(deg + c, 1.0f);
    }
}

__global__ void k_dinv(float* deg, int n) {
    int i = blockIdx.x * blockDim.x + threadIdx.x;
    if (i < n) deg[i] = rsqrtf(deg[i]);
}

// ---------------------------------------------------------------------------
// GEMM: H[n,64] = act(A[n,K]) @ W[K,64]      (act = relu if RELU)
// 64x64 output tile per block, 256 threads, 4x4 register tile, K tiled at 64.
// ---------------------------------------------------------------------------
template <int K, bool RELU>
__global__ void k_gemm(const float* __restrict__ A, const float* __restrict__ W,
                       float* __restrict__ H, int n) {
    __shared__ float As[64][68];   // +4 pad: conflict-free, float4-aligned
    __shared__ float Ws[64][64];

    const int t  = threadIdx.x;
    const int tx = t & 15;         // col group 0..15
    const int ty = t >> 4;         // row group 0..15
    const int rowBase = blockIdx.x * 64;

    float acc[4][4];
#pragma unroll
    for (int i = 0; i < 4; i++)
#pragma unroll
        for (int j = 0; j < 4; j++) acc[i][j] = 0.0f;

#pragma unroll
    for (int kc = 0; kc < K; kc += 64) {
        // load A tile: 64 rows x 64 k = 4096 floats
#pragma unroll
        for (int it = 0; it < 4; it++) {
            int idx = (it * 256 + t) * 4;          // 0..4095
            int r = idx >> 6;                      // /64
            int k = idx & 63;
            int grow = rowBase + r;
            float4 v = make_float4(0.f, 0.f, 0.f, 0.f);
            if (grow < n) {
                v = *reinterpret_cast<const float4*>(A + (long long)grow * K + kc + k);
                if (RELU) {
                    v.x = fmaxf(v.x, 0.f); v.y = fmaxf(v.y, 0.f);
                    v.z = fmaxf(v.z, 0.f); v.w = fmaxf(v.w, 0.f);
                }
            }
            *reinterpret_cast<float4*>(&As[r][k]) = v;
        }
        // load W tile: 64 k x 64 cols
#pragma unroll
        for (int it = 0; it < 4; it++) {
            int idx = (it * 256 + t) * 4;
            int k = idx >> 6;
            int c = idx & 63;
            *reinterpret_cast<float4*>(&Ws[k][c]) =
                *reinterpret_cast<const float4*>(W + (long long)(kc + k) * 64 + c);
        }
        __syncthreads();

#pragma unroll
        for (int k = 0; k < 64; k++) {
            float a0 = As[ty * 4 + 0][k];
            float a1 = As[ty * 4 + 1][k];
            float a2 = As[ty * 4 + 2][k];
            float a3 = As[ty * 4 + 3][k];
            float4 w = *reinterpret_cast<const float4*>(&Ws[k][tx * 4]);
            acc[0][0] += a0 * w.x; acc[0][1] += a0 * w.y; acc[0][2] += a0 * w.z; acc[0][3] += a0 * w.w;
            acc[1][0] += a1 * w.x; acc[1][1] += a1 * w.y; acc[1][2] += a1 * w.z; acc[1][3] += a1 * w.w;
            acc[2][0] += a2 * w.x; acc[2][1] += a2 * w.y; acc[2][2] += a2 * w.z; acc[2][3] += a2 * w.w;
            acc[3][0] += a3 * w.x; acc[3][1] += a3 * w.y; acc[3][2] += a3 * w.z; acc[3][3] += a3 * w.w;
        }
        __syncthreads();
    }

#pragma unroll
    for (int i = 0; i < 4; i++) {
        int grow = rowBase + ty * 4 + i;
        if (grow < n) {
            float4 v = make_float4(acc[i][0], acc[i][1], acc[i][2], acc[i][3]);
            *reinterpret_cast<float4*>(H + (long long)grow * 64 + tx * 4) = v;
        }
    }
}

// ---------------------------------------------------------------------------
// agg init: agg[i] = h[i] * dinv[i]^2 + b      (self-loop term + bias)
// ---------------------------------------------------------------------------
__global__ void k_agg_init(const float* __restrict__ h, const float* __restrict__ dinv,
                           const float* __restrict__ b, float* __restrict__ agg, int n) {
    int idx = blockIdx.x * blockDim.x + threadIdx.x;   // over n*16 float4s
    if (idx >= n * 16) return;
    int node = idx >> 4;
    int c4   = idx & 15;
    float di = dinv[node];
    float s = di * di;
    float4 hv = reinterpret_cast<const float4*>(h)[idx];
    float4 bv = reinterpret_cast<const float4*>(b)[c4];
    float4 o;
    o.x = hv.x * s + bv.x; o.y = hv.y * s + bv.y;
    o.z = hv.z * s + bv.z; o.w = hv.w * s + bv.w;
    reinterpret_cast<float4*>(agg)[idx] = o;
}

// ---------------------------------------------------------------------------
// edge scatter: agg[col] += h[row] * dinv[row]*dinv[col]
// 16 threads per edge, one float4 load + one red.global.v4 each
// ---------------------------------------------------------------------------
__global__ void k_edge(const int* __restrict__ ei, int E,
                       const float* __restrict__ dinv,
                       const float* __restrict__ h, float* __restrict__ agg) {
    int gid = blockIdx.x * blockDim.x + threadIdx.x;
    int e  = gid >> 4;
    int c4 = gid & 15;
    if (e >= E) return;
    int r = ei[e];
    int c = ei[E + e];
    float coef = dinv[r] * dinv[c];
    float4 v = reinterpret_cast<const float4*>(h)[r * 16 + c4];
    float mx = v.x * coef, my = v.y * coef, mz = v.z * coef, mw = v.w * coef;
    float* dst = agg + (long long)c * 64 + c4 * 4;
    asm volatile("red.global.add.v4.f32 [%0], {%1, %2, %3, %4};"
                 :: "l"(dst), "f"(mx), "f"(my), "f"(mz), "f"(mw) : "memory");
}

// ---------------------------------------------------------------------------
// pooling: segment-sum over sorted batch ids, shared pre-aggregation
// ---------------------------------------------------------------------------
#define POOL_NODES 512
__global__ void k_pool_zero(float* pooled, float* cnt) {
    int i = blockIdx.x * blockDim.x + threadIdx.x;
    if (i < N_GRAPHS * HID) pooled[i] = 0.f;
    if (i < N_GRAPHS) cnt[i] = 0.f;
}

__global__ void k_pool(const float* __restrict__ agg, const int* __restrict__ batch,
                       int n, float* __restrict__ pooled, float* __restrict__ cnt) {
    __shared__ float acc[N_GRAPHS * HID];   // 16 KB
    __shared__ float cs[N_GRAPHS];
    for (int i = threadIdx.x; i < N_GRAPHS * HID; i += blockDim.x) acc[i] = 0.f;
    if (threadIdx.x < N_GRAPHS) cs[threadIdx.x] = 0.f;
    __syncthreads();

    int base = blockIdx.x * POOL_NODES;
    int ch  = threadIdx.x & 63;
    int sub = threadIdx.x >> 6;          // 0..3
    for (int i = sub; i < POOL_NODES; i += 4) {
        int node = base + i;
        if (node >= n) break;
        int g = batch[node];
        float v = agg[(long long)node * 64 + ch];
        atomicAdd(&acc[g * 64 + ch], v);
        if (ch == 0) atomicAdd(&cs[g], 1.0f);
    }
    __syncthreads();

    for (int i = threadIdx.x; i < N_GRAPHS * HID; i += blockDim.x) {
        float v = acc[i];
        if (v != 0.f) atomicAdd(&pooled[i], v);
    }
    if (threadIdx.x < N_GRAPHS) {
        float v = cs[threadIdx.x];
        if (v != 0.f) atomicAdd(&cnt[threadIdx.x], v);
    }
}

// ---------------------------------------------------------------------------
// head: out[g,o] = (pooled[g]/max(cnt,1)) @ Wlin + blin
// ---------------------------------------------------------------------------
__global__ void k_final(const float* __restrict__ pooled, const float* __restrict__ cnt,
                        const float* __restrict__ Wlin, const float* __restrict__ blin,
                        float* __restrict__ out) {
    int t = threadIdx.x;                 // 128 threads
    int g = t >> 1;
    int o = t & 1;
    float inv = 1.0f / fmaxf(cnt[g], 1.0f);
    float s = 0.0f;
#pragma unroll
    for (int c = 0; c < HID; c++) s += pooled[g * 64 + c] * Wlin[c * 2 + o];
    out[g * 2 + o] = s * inv + blin[o];
}

// ---------------------------------------------------------------------------
extern "C" void kernel_launch(void* const* d_in, const int* in_sizes, int n_in,
                              void* d_out, int out_size) {
    const float* x    = (const float*)d_in[0];
    const int*   ei   = (const int*)d_in[1];     // int32! (JAX x64 disabled)
    const int*   batch= (const int*)d_in[2];     // int32!
    const float* W1   = (const float*)d_in[3];
    const float* b1   = (const float*)d_in[4];
    const float* W2   = (const float*)d_in[5];
    const float* b2   = (const float*)d_in[6];
    const float* W3   = (const float*)d_in[7];
    const float* b3   = (const float*)d_in[8];
    const float* Wlin = (const float*)d_in[9];
    const float* blin = (const float*)d_in[10];
    float* out = (float*)d_out;

    const int n = in_sizes[2];            // batch vector length = N_NODES
    const int E = in_sizes[1] / 2;

    float* h    = nullptr; cudaGetSymbolAddress((void**)&h,    g_h);
    float* agg  = nullptr; cudaGetSymbolAddress((void**)&agg,  g_agg);
    float* dinv = nullptr; cudaGetSymbolAddress((void**)&dinv, g_dinv);
    float* pooled = nullptr; cudaGetSymbolAddress((void**)&pooled, g_pooled);
    float* cnt  = nullptr; cudaGetSymbolAddress((void**)&cnt,  g_cnt);

    const int T = 256;
    // degrees
    k_deg_init<<<(n + T - 1) / T, T>>>(dinv, n);
    k_deg_scatter<<<(E + T - 1) / T, T>>>(ei, E, dinv);
    k_dinv<<<(n + T - 1) / T, T>>>(dinv, n);

    int gemmGrid = (n + 63) / 64;
    int vecGrid  = (n * 16 + T - 1) / T;
    int edgeGrid = (E * 16 + T - 1) / T;

    // layer 1: h = x @ W1 ; agg = h*dinv^2 + b1 ; scatter
    k_gemm<128, false><<<gemmGrid, T>>>(x, W1, h, n);
    k_agg_init<<<vecGrid, T>>>(h, dinv, b1, agg, n);
    k_edge<<<edgeGrid, T>>>(ei, E, dinv, h, agg);

    // layer 2: h = relu(agg) @ W2 ; ...
    k_gemm<64, true><<<gemmGrid, T>>>(agg, W2, h, n);
    k_agg_init<<<vecGrid, T>>>(h, dinv, b2, agg, n);
    k_edge<<<edgeGrid, T>>>(ei, E, dinv, h, agg);

    // layer 3: h = relu(agg) @ W3 ; ... (no relu after)
    k_gemm<64, true><<<gemmGrid, T>>>(agg, W3, h, n);
    k_agg_init<<<vecGrid, T>>>(h, dinv, b3, agg, n);
    k_edge<<<edgeGrid, T>>>(ei, E, dinv, h, agg);

    // pooling + head
    k_pool_zero<<<(N_GRAPHS * HID + T - 1) / T, T>>>(pooled, cnt);
    k_pool<<<(n + POOL_NODES - 1) / POOL_NODES, T>>>(agg, batch, n, pooled, cnt);
    k_final<<<1, 128>>>(pooled, cnt, Wlin, blin, out);
}

// round 4
// speedup vs baseline: 1.4946x; 1.4946x over previous
#include <cuda_runtime.h>
#include <cuda_bf16.h>
#include <cstdint>

#define MAX_NODES 100000
#define MAX_EDGES 1600000
#define HID 64
#define N_GRAPHS 64

// Scratch (no cudaMalloc allowed)
__device__ float  g_h[MAX_NODES * HID];       // 25.6 MB
__device__ float  g_agg[MAX_NODES * HID];     // 25.6 MB
__device__ float  g_dinv[MAX_NODES];
__device__ int    g_cnt[MAX_NODES];
__device__ int    g_off[MAX_NODES + 1];
__device__ int    g_cur[MAX_NODES];
__device__ int    g_bsum[512];
__device__ int    g_bbase[512];
__device__ float2 g_csr[MAX_EDGES];           // {src_as_float_bits, coef} 12.8 MB
__device__ float  g_pooled[N_GRAPHS * HID];
__device__ float  g_cntf[N_GRAPHS];

// ---------------------------------------------------------------------------
// CSR build: count -> scan -> fill
// ---------------------------------------------------------------------------
__global__ void k_zero_cnt(int* cnt, int n) {
    int i = blockIdx.x * blockDim.x + threadIdx.x;
    if (i < n) cnt[i] = 0;
}

__global__ void k_count(const int* __restrict__ ei, int E, int* cnt) {
    int e = blockIdx.x * blockDim.x + threadIdx.x;
    if (e < E) atomicAdd(cnt + ei[E + e], 1);
}

// per-block exclusive scan of 256 counts; writes partial off + block sums
__global__ void k_scan_local(const int* __restrict__ cnt, int n,
                             int* __restrict__ off, int* __restrict__ bsum) {
    __shared__ int s[256];
    int i = blockIdx.x * 256 + threadIdx.x;
    int v = (i < n) ? cnt[i] : 0;
    s[threadIdx.x] = v;
    __syncthreads();
    // Hillis-Steele inclusive scan
    int val = v;
#pragma unroll
    for (int d = 1; d < 256; d <<= 1) {
        int t = (threadIdx.x >= d) ? s[threadIdx.x - d] : 0;
        __syncthreads();
        val += t;
        s[threadIdx.x] = val;
        __syncthreads();
    }
    if (i < n) off[i] = val - v;          // exclusive
    if (threadIdx.x == 255) bsum[blockIdx.x] = val;
}

// single-block exclusive scan of block sums (<=512)
__global__ void k_scan_block(int* __restrict__ bsum, int nb, int* __restrict__ bbase) {
    __shared__ int s[512];
    int t = threadIdx.x;
    int v = (t < nb) ? bsum[t] : 0;
    s[t] = v;
    __syncthreads();
    int val = v;
#pragma unroll
    for (int d = 1; d < 512; d <<= 1) {
        int x = (t >= d) ? s[t - d] : 0;
        __syncthreads();
        val += x;
        s[t] = val;
        __syncthreads();
    }
    if (t < nb) bbase[t] = val - v;       // exclusive
}

// finalize: add block bases, init cursor, compute dinv, set off[n]
__global__ void k_scan_add(const int* __restrict__ cnt, int n,
                           int* __restrict__ off, const int* __restrict__ bbase,
                           int* __restrict__ cur, float* __restrict__ dinv) {
    int i = blockIdx.x * blockDim.x + threadIdx.x;
    if (i >= n) return;
    int o = off[i] + bbase[i >> 8];
    off[i] = o;
    cur[i] = o;
    dinv[i] = rsqrtf(1.0f + (float)cnt[i]);
    if (i == n - 1) off[n] = o + cnt[i];
}

__global__ void k_fill(const int* __restrict__ ei, int E,
                       const float* __restrict__ dinv,
                       int* __restrict__ cur, float2* __restrict__ csr) {
    int e = blockIdx.x * blockDim.x + threadIdx.x;
    if (e >= E) return;
    int r = ei[e];
    int c = ei[E + e];
    float coef = dinv[r] * dinv[c];
    int pos = atomicAdd(cur + c, 1);
    csr[pos] = make_float2(__int_as_float(r), coef);
}

// ---------------------------------------------------------------------------
// GEMM: H[n,64] = act(A[n,K]) @ W[K,64]
// ---------------------------------------------------------------------------
template <int K, bool RELU>
__global__ void __launch_bounds__(256, 4)
k_gemm(const float* __restrict__ A, const float* __restrict__ W,
       float* __restrict__ H, int n) {
    __shared__ float As[64][68];
    __shared__ float Ws[64][64];

    const int t  = threadIdx.x;
    const int tx = t & 15;
    const int ty = t >> 4;
    const int rowBase = blockIdx.x * 64;

    float acc[4][4];
#pragma unroll
    for (int i = 0; i < 4; i++)
#pragma unroll
        for (int j = 0; j < 4; j++) acc[i][j] = 0.0f;

#pragma unroll
    for (int kc = 0; kc < K; kc += 64) {
#pragma unroll
        for (int it = 0; it < 4; it++) {
            int idx = (it * 256 + t) * 4;
            int r = idx >> 6;
            int k = idx & 63;
            int grow = rowBase + r;
            float4 v = make_float4(0.f, 0.f, 0.f, 0.f);
            if (grow < n) {
                v = *reinterpret_cast<const float4*>(A + (long long)grow * K + kc + k);
                if (RELU) {
                    v.x = fmaxf(v.x, 0.f); v.y = fmaxf(v.y, 0.f);
                    v.z = fmaxf(v.z, 0.f); v.w = fmaxf(v.w, 0.f);
                }
            }
            *reinterpret_cast<float4*>(&As[r][k]) = v;
        }
#pragma unroll
        for (int it = 0; it < 4; it++) {
            int idx = (it * 256 + t) * 4;
            int k = idx >> 6;
            int c = idx & 63;
            *reinterpret_cast<float4*>(&Ws[k][c]) =
                *reinterpret_cast<const float4*>(W + (long long)(kc + k) * 64 + c);
        }
        __syncthreads();

#pragma unroll
        for (int k = 0; k < 64; k++) {
            float a0 = As[ty * 4 + 0][k];
            float a1 = As[ty * 4 + 1][k];
            float a2 = As[ty * 4 + 2][k];
            float a3 = As[ty * 4 + 3][k];
            float4 w = *reinterpret_cast<const float4*>(&Ws[k][tx * 4]);
            acc[0][0] += a0 * w.x; acc[0][1] += a0 * w.y; acc[0][2] += a0 * w.z; acc[0][3] += a0 * w.w;
            acc[1][0] += a1 * w.x; acc[1][1] += a1 * w.y; acc[1][2] += a1 * w.z; acc[1][3] += a1 * w.w;
            acc[2][0] += a2 * w.x; acc[2][1] += a2 * w.y; acc[2][2] += a2 * w.z; acc[2][3] += a2 * w.w;
            acc[3][0] += a3 * w.x; acc[3][1] += a3 * w.y; acc[3][2] += a3 * w.z; acc[3][3] += a3 * w.w;
        }
        __syncthreads();
    }

#pragma unroll
    for (int i = 0; i < 4; i++) {
        int grow = rowBase + ty * 4 + i;
        if (grow < n) {
            float4 v = make_float4(acc[i][0], acc[i][1], acc[i][2], acc[i][3]);
            *reinterpret_cast<float4*>(H + (long long)grow * 64 + tx * 4) = v;
        }
    }
}

// ---------------------------------------------------------------------------
// CSR gather: agg[node] = sum_{nbr} h[src]*coef + h[node]*dinv^2 + b
// 16 threads per node, one float4 each, no atomics.
// ---------------------------------------------------------------------------
__global__ void k_gather(const int* __restrict__ off, const float2* __restrict__ csr,
                         const float* __restrict__ dinv, const float* __restrict__ h,
                         const float* __restrict__ b, float* __restrict__ agg, int n) {
    int gid = blockIdx.x * blockDim.x + threadIdx.x;
    int node = gid >> 4;
    int c4   = gid & 15;
    if (node >= n) return;

    float di = dinv[node];
    float4 hv = reinterpret_cast<const float4*>(h)[node * 16 + c4];
    float4 bv = reinterpret_cast<const float4*>(b)[c4];
    float s = di * di;
    float4 acc;
    acc.x = hv.x * s + bv.x; acc.y = hv.y * s + bv.y;
    acc.z = hv.z * s + bv.z; acc.w = hv.w * s + bv.w;

    int k   = off[node];
    int end = off[node + 1];
    if (k < end) {
        float2 d = csr[k];                       // broadcast across 16 lanes
        for (; k < end; ) {
            int kn = k + 1;
            float2 dn = (kn < end) ? csr[kn] : d;  // prefetch next descriptor
            int r = __float_as_int(d.x);
            float coef = d.y;
            float4 v = reinterpret_cast<const float4*>(h)[r * 16 + c4];
            acc.x += v.x * coef; acc.y += v.y * coef;
            acc.z += v.z * coef; acc.w += v.w * coef;
            d = dn;
            k = kn;
        }
    }
    reinterpret_cast<float4*>(agg)[node * 16 + c4] = acc;
}

// ---------------------------------------------------------------------------
// pooling + head
// ---------------------------------------------------------------------------
#define POOL_NODES 512
__global__ void k_pool_zero(float* pooled, float* cntf) {
    int i = blockIdx.x * blockDim.x + threadIdx.x;
    if (i < N_GRAPHS * HID) pooled[i] = 0.f;
    if (i < N_GRAPHS) cntf[i] = 0.f;
}

__global__ void k_pool(const float* __restrict__ agg, const int* __restrict__ batch,
                       int n, float* __restrict__ pooled, float* __restrict__ cntf) {
    __shared__ float acc[N_GRAPHS * HID];
    __shared__ float cs[N_GRAPHS];
    for (int i = threadIdx.x; i < N_GRAPHS * HID; i += blockDim.x) acc[i] = 0.f;
    if (threadIdx.x < N_GRAPHS) cs[threadIdx.x] = 0.f;
    __syncthreads();

    int base = blockIdx.x * POOL_NODES;
    int ch  = threadIdx.x & 63;
    int sub = threadIdx.x >> 6;
    for (int i = sub; i < POOL_NODES; i += 4) {
        int node = base + i;
        if (node >= n) break;
        int g = batch[node];
        float v = agg[(long long)node * 64 + ch];
        atomicAdd(&acc[g * 64 + ch], v);
        if (ch == 0) atomicAdd(&cs[g], 1.0f);
    }
    __syncthreads();

    for (int i = threadIdx.x; i < N_GRAPHS * HID; i += blockDim.x) {
        float v = acc[i];
        if (v != 0.f) atomicAdd(&pooled[i], v);
    }
    if (threadIdx.x < N_GRAPHS) {
        float v = cs[threadIdx.x];
        if (v != 0.f) atomicAdd(&cntf[threadIdx.x], v);
    }
}

__global__ void k_final(const float* __restrict__ pooled, const float* __restrict__ cntf,
                        const float* __restrict__ Wlin, const float* __restrict__ blin,
                        float* __restrict__ out) {
    int t = threadIdx.x;
    int g = t >> 1;
    int o = t & 1;
    float inv = 1.0f / fmaxf(cntf[g], 1.0f);
    float s = 0.0f;
#pragma unroll
    for (int c = 0; c < HID; c++) s += pooled[g * 64 + c] * Wlin[c * 2 + o];
    out[g * 2 + o] = s * inv + blin[o];
}

// ---------------------------------------------------------------------------
extern "C" void kernel_launch(void* const* d_in, const int* in_sizes, int n_in,
                              void* d_out, int out_size) {
    const float* x    = (const float*)d_in[0];
    const int*   ei   = (const int*)d_in[1];
    const int*   batch= (const int*)d_in[2];
    const float* W1   = (const float*)d_in[3];
    const float* b1   = (const float*)d_in[4];
    const float* W2   = (const float*)d_in[5];
    const float* b2   = (const float*)d_in[6];
    const float* W3   = (const float*)d_in[7];
    const float* b3   = (const float*)d_in[8];
    const float* Wlin = (const float*)d_in[9];
    const float* blin = (const float*)d_in[10];
    float* out = (float*)d_out;

    const int n = in_sizes[2];
    const int E = in_sizes[1] / 2;

    float*  h    = nullptr; cudaGetSymbolAddress((void**)&h,    g_h);
    float*  agg  = nullptr; cudaGetSymbolAddress((void**)&agg,  g_agg);
    float*  dinv = nullptr; cudaGetSymbolAddress((void**)&dinv, g_dinv);
    int*    cnt  = nullptr; cudaGetSymbolAddress((void**)&cnt,  g_cnt);
    int*    off  = nullptr; cudaGetSymbolAddress((void**)&off,  g_off);
    int*    cur  = nullptr; cudaGetSymbolAddress((void**)&cur,  g_cur);
    int*    bsum = nullptr; cudaGetSymbolAddress((void**)&bsum, g_bsum);
    int*    bbase= nullptr; cudaGetSymbolAddress((void**)&bbase,g_bbase);
    float2* csr  = nullptr; cudaGetSymbolAddress((void**)&csr,  g_csr);
    float*  pooled = nullptr; cudaGetSymbolAddress((void**)&pooled, g_pooled);
    float*  cntf = nullptr; cudaGetSymbolAddress((void**)&cntf, g_cntf);

    const int T = 256;
    const int nb = (n + 255) / 256;

    // CSR build
    k_zero_cnt<<<(n + T - 1) / T, T>>>(cnt, n);
    k_count<<<(E + T - 1) / T, T>>>(ei, E, cnt);
    k_scan_local<<<nb, 256>>>(cnt, n, off, bsum);
    k_scan_block<<<1, 512>>>(bsum, nb, bbase);
    k_scan_add<<<(n + T - 1) / T, T>>>(cnt, n, off, bbase, cur, dinv);
    k_fill<<<(E + T - 1) / T, T>>>(ei, E, dinv, cur, csr);

    int gemmGrid   = (n + 63) / 64;
    int gatherGrid = (n * 16 + T - 1) / T;

    // layer 1
    k_gemm<128, false><<<gemmGrid, T>>>(x, W1, h, n);
    k_gather<<<gatherGrid, T>>>(off, csr, dinv, h, b1, agg, n);
    // layer 2
    k_gemm<64, true><<<gemmGrid, T>>>(agg, W2, h, n);
    k_gather<<<gatherGrid, T>>>(off, csr, dinv, h, b2, agg, n);
    // layer 3
    k_gemm<64, true><<<gemmGrid, T>>>(agg, W3, h, n);
    k_gather<<<gatherGrid, T>>>(off, csr, dinv, h, b3, agg, n);

    // pooling + head
    k_pool_zero<<<(N_GRAPHS * HID + T - 1) / T, T>>>(pooled, cntf);
    k_pool<<<(n + POOL_NODES - 1) / POOL_NODES, T>>>(agg, batch, n, pooled, cntf);
    k_final<<<1, 128>>>(pooled, cntf, Wlin, blin, out);
}

// round 5
// speedup vs baseline: 1.5745x; 1.0535x over previous
#include <cuda_runtime.h>
#include <cuda_bf16.h>
#include <cstdint>

#define MAX_NODES 100000
#define MAX_EDGES 1600000
#define HID 64
#define N_GRAPHS 64

// Scratch (no cudaMalloc allowed)
__device__ float  g_h[MAX_NODES * HID];       // 25.6 MB
__device__ float  g_agg[MAX_NODES * HID];     // 25.6 MB
__device__ float  g_dinv[MAX_NODES];
__device__ int    g_cnt[MAX_NODES];
__device__ int    g_off[MAX_NODES + 1];
__device__ int    g_cur[MAX_NODES];
__device__ int    g_bsum[512];
__device__ int    g_bbase[512];
__device__ float2 g_csr[MAX_EDGES];           // {src_as_int_bits, coef} 12.8 MB
__device__ float  g_pooled[N_GRAPHS * HID];
__device__ float  g_cntf[N_GRAPHS];

// ---------------------------------------------------------------------------
// CSR build: count -> scan -> fill
// ---------------------------------------------------------------------------
__global__ void k_count(const int* __restrict__ ei, int E, int* cnt) {
    int e = blockIdx.x * blockDim.x + threadIdx.x;
    if (e < E) atomicAdd(cnt + ei[E + e], 1);
}

// per-block exclusive scan of 256 counts; writes partial off + block sums
__global__ void k_scan_local(const int* __restrict__ cnt, int n,
                             int* __restrict__ off, int* __restrict__ bsum) {
    __shared__ int s[256];
    int i = blockIdx.x * 256 + threadIdx.x;
    int v = (i < n) ? cnt[i] : 0;
    s[threadIdx.x] = v;
    __syncthreads();
    int val = v;
#pragma unroll
    for (int d = 1; d < 256; d <<= 1) {
        int t = (threadIdx.x >= d) ? s[threadIdx.x - d] : 0;
        __syncthreads();
        val += t;
        s[threadIdx.x] = val;
        __syncthreads();
    }
    if (i < n) off[i] = val - v;          // exclusive
    if (threadIdx.x == 255) bsum[blockIdx.x] = val;
}

// single-block exclusive scan of block sums (<=512)
__global__ void k_scan_block(int* __restrict__ bsum, int nb, int* __restrict__ bbase) {
    __shared__ int s[512];
    int t = threadIdx.x;
    int v = (t < nb) ? bsum[t] : 0;
    s[t] = v;
    __syncthreads();
    int val = v;
#pragma unroll
    for (int d = 1; d < 512; d <<= 1) {
        int x = (t >= d) ? s[t - d] : 0;
        __syncthreads();
        val += x;
        s[t] = val;
        __syncthreads();
    }
    if (t < nb) bbase[t] = val - v;       // exclusive
}

// finalize: add block bases, init cursor, compute dinv, set off[n]
__global__ void k_scan_add(const int* __restrict__ cnt, int n,
                           int* __restrict__ off, const int* __restrict__ bbase,
                           int* __restrict__ cur, float* __restrict__ dinv) {
    int i = blockIdx.x * blockDim.x + threadIdx.x;
    if (i >= n) return;
    int o = off[i] + bbase[i >> 8];
    off[i] = o;
    cur[i] = o;
    dinv[i] = rsqrtf(1.0f + (float)cnt[i]);
    if (i == n - 1) off[n] = o + cnt[i];
}

__global__ void k_fill(const int* __restrict__ ei, int E,
                       const float* __restrict__ dinv,
                       int* __restrict__ cur, float2* __restrict__ csr) {
    int e = blockIdx.x * blockDim.x + threadIdx.x;
    if (e >= E) return;
    int r = ei[e];
    int c = ei[E + e];
    float coef = dinv[r] * dinv[c];
    int pos = atomicAdd(cur + c, 1);
    csr[pos] = make_float2(__int_as_float(r), coef);
}

// ---------------------------------------------------------------------------
// GEMM: H[n,64] = act(A[n,K]) @ W[K,64]
// ---------------------------------------------------------------------------
template <int K, bool RELU>
__global__ void __launch_bounds__(256, 4)
k_gemm(const float* __restrict__ A, const float* __restrict__ W,
       float* __restrict__ H, int n) {
    __shared__ float As[64][68];
    __shared__ float Ws[64][64];

    const int t  = threadIdx.x;
    const int tx = t & 15;
    const int ty = t >> 4;
    const int rowBase = blockIdx.x * 64;

    float acc[4][4];
#pragma unroll
    for (int i = 0; i < 4; i++)
#pragma unroll
        for (int j = 0; j < 4; j++) acc[i][j] = 0.0f;

#pragma unroll
    for (int kc = 0; kc < K; kc += 64) {
#pragma unroll
        for (int it = 0; it < 4; it++) {
            int idx = (it * 256 + t) * 4;
            int r = idx >> 6;
            int k = idx & 63;
            int grow = rowBase + r;
            float4 v = make_float4(0.f, 0.f, 0.f, 0.f);
            if (grow < n) {
                v = *reinterpret_cast<const float4*>(A + (long long)grow * K + kc + k);
                if (RELU) {
                    v.x = fmaxf(v.x, 0.f); v.y = fmaxf(v.y, 0.f);
                    v.z = fmaxf(v.z, 0.f); v.w = fmaxf(v.w, 0.f);
                }
            }
            *reinterpret_cast<float4*>(&As[r][k]) = v;
        }
#pragma unroll
        for (int it = 0; it < 4; it++) {
            int idx = (it * 256 + t) * 4;
            int k = idx >> 6;
            int c = idx & 63;
            *reinterpret_cast<float4*>(&Ws[k][c]) =
                *reinterpret_cast<const float4*>(W + (long long)(kc + k) * 64 + c);
        }
        __syncthreads();

#pragma unroll
        for (int k = 0; k < 64; k++) {
            float a0 = As[ty * 4 + 0][k];
            float a1 = As[ty * 4 + 1][k];
            float a2 = As[ty * 4 + 2][k];
            float a3 = As[ty * 4 + 3][k];
            float4 w = *reinterpret_cast<const float4*>(&Ws[k][tx * 4]);
            acc[0][0] += a0 * w.x; acc[0][1] += a0 * w.y; acc[0][2] += a0 * w.z; acc[0][3] += a0 * w.w;
            acc[1][0] += a1 * w.x; acc[1][1] += a1 * w.y; acc[1][2] += a1 * w.z; acc[1][3] += a1 * w.w;
            acc[2][0] += a2 * w.x; acc[2][1] += a2 * w.y; acc[2][2] += a2 * w.z; acc[2][3] += a2 * w.w;
            acc[3][0] += a3 * w.x; acc[3][1] += a3 * w.y; acc[3][2] += a3 * w.z; acc[3][3] += a3 * w.w;
        }
        __syncthreads();
    }

#pragma unroll
    for (int i = 0; i < 4; i++) {
        int grow = rowBase + ty * 4 + i;
        if (grow < n) {
            float4 v = make_float4(acc[i][0], acc[i][1], acc[i][2], acc[i][3]);
            *reinterpret_cast<float4*>(H + (long long)grow * 64 + tx * 4) = v;
        }
    }
}

// ---------------------------------------------------------------------------
// CSR gather: agg[node] = sum_{nbr} h[src]*coef + h[node]*dinv^2 + b
// 16 threads per node, one float4 each, no atomics. Unrolled x2 for MLP.
// ---------------------------------------------------------------------------
__global__ void k_gather(const int* __restrict__ off, const float2* __restrict__ csr,
                         const float* __restrict__ dinv, const float* __restrict__ h,
                         const float* __restrict__ b, float* __restrict__ agg, int n) {
    int gid = blockIdx.x * blockDim.x + threadIdx.x;
    int node = gid >> 4;
    int c4   = gid & 15;
    if (node >= n) return;

    float di = dinv[node];
    float4 hv = reinterpret_cast<const float4*>(h)[node * 16 + c4];
    float4 bv = reinterpret_cast<const float4*>(b)[c4];
    float s = di * di;
    float4 acc;
    acc.x = hv.x * s + bv.x; acc.y = hv.y * s + bv.y;
    acc.z = hv.z * s + bv.z; acc.w = hv.w * s + bv.w;

    int k   = off[node];
    int end = off[node + 1];

    // 2-wide unroll: two independent h-loads in flight per iteration
    for (; k + 2 <= end; k += 2) {
        float2 d0 = csr[k];
        float2 d1 = csr[k + 1];
        int r0 = __float_as_int(d0.x);
        int r1 = __float_as_int(d1.x);
        float4 v0 = reinterpret_cast<const float4*>(h)[r0 * 16 + c4];
        float4 v1 = reinterpret_cast<const float4*>(h)[r1 * 16 + c4];
        acc.x += v0.x * d0.y; acc.y += v0.y * d0.y;
        acc.z += v0.z * d0.y; acc.w += v0.w * d0.y;
        acc.x += v1.x * d1.y; acc.y += v1.y * d1.y;
        acc.z += v1.z * d1.y; acc.w += v1.w * d1.y;
    }
    if (k < end) {
        float2 d = csr[k];
        int r = __float_as_int(d.x);
        float4 v = reinterpret_cast<const float4*>(h)[r * 16 + c4];
        acc.x += v.x * d.y; acc.y += v.y * d.y;
        acc.z += v.z * d.y; acc.w += v.w * d.y;
    }
    reinterpret_cast<float4*>(agg)[node * 16 + c4] = acc;
}

// ---------------------------------------------------------------------------
// pooling + head
// ---------------------------------------------------------------------------
#define POOL_NODES 512
__global__ void k_pool(const float* __restrict__ agg, const int* __restrict__ batch,
                       int n, float* __restrict__ pooled, float* __restrict__ cntf) {
    __shared__ float acc[N_GRAPHS * HID];
    __shared__ float cs[N_GRAPHS];
    for (int i = threadIdx.x; i < N_GRAPHS * HID; i += blockDim.x) acc[i] = 0.f;
    if (threadIdx.x < N_GRAPHS) cs[threadIdx.x] = 0.f;
    __syncthreads();

    int base = blockIdx.x * POOL_NODES;
    int ch  = threadIdx.x & 63;
    int sub = threadIdx.x >> 6;
    for (int i = sub; i < POOL_NODES; i += 4) {
        int node = base + i;
        if (node >= n) break;
        int g = batch[node];
        float v = agg[(long long)node * 64 + ch];
        atomicAdd(&acc[g * 64 + ch], v);
        if (ch == 0) atomicAdd(&cs[g], 1.0f);
    }
    __syncthreads();

    for (int i = threadIdx.x; i < N_GRAPHS * HID; i += blockDim.x) {
        float v = acc[i];
        if (v != 0.f) atomicAdd(&pooled[i], v);
    }
    if (threadIdx.x < N_GRAPHS) {
        float v = cs[threadIdx.x];
        if (v != 0.f) atomicAdd(&cntf[threadIdx.x], v);
    }
}

__global__ void k_final(const float* __restrict__ pooled, const float* __restrict__ cntf,
                        const float* __restrict__ Wlin, const float* __restrict__ blin,
                        float* __restrict__ out) {
    int t = threadIdx.x;
    int g = t >> 1;
    int o = t & 1;
    float inv = 1.0f / fmaxf(cntf[g], 1.0f);
    float s = 0.0f;
#pragma unroll
    for (int c = 0; c < HID; c++) s += pooled[g * 64 + c] * Wlin[c * 2 + o];
    out[g * 2 + o] = s * inv + blin[o];
}

// ---------------------------------------------------------------------------
extern "C" void kernel_launch(void* const* d_in, const int* in_sizes, int n_in,
                              void* d_out, int out_size) {
    const float* x    = (const float*)d_in[0];
    const int*   ei   = (const int*)d_in[1];
    const int*   batch= (const int*)d_in[2];
    const float* W1   = (const float*)d_in[3];
    const float* b1   = (const float*)d_in[4];
    const float* W2   = (const float*)d_in[5];
    const float* b2   = (const float*)d_in[6];
    const float* W3   = (const float*)d_in[7];
    const float* b3   = (const float*)d_in[8];
    const float* Wlin = (const float*)d_in[9];
    const float* blin = (const float*)d_in[10];
    float* out = (float*)d_out;

    const int n = in_sizes[2];
    const int E = in_sizes[1] / 2;

    float*  h    = nullptr; cudaGetSymbolAddress((void**)&h,    g_h);
    float*  agg  = nullptr; cudaGetSymbolAddress((void**)&agg,  g_agg);
    float*  dinv = nullptr; cudaGetSymbolAddress((void**)&dinv, g_dinv);
    int*    cnt  = nullptr; cudaGetSymbolAddress((void**)&cnt,  g_cnt);
    int*    off  = nullptr; cudaGetSymbolAddress((void**)&off,  g_off);
    int*    cur  = nullptr; cudaGetSymbolAddress((void**)&cur,  g_cur);
    int*    bsum = nullptr; cudaGetSymbolAddress((void**)&bsum, g_bsum);
    int*    bbase= nullptr; cudaGetSymbolAddress((void**)&bbase,g_bbase);
    float2* csr  = nullptr; cudaGetSymbolAddress((void**)&csr,  g_csr);
    float*  pooled = nullptr; cudaGetSymbolAddress((void**)&pooled, g_pooled);
    float*  cntf = nullptr; cudaGetSymbolAddress((void**)&cntf, g_cntf);

    // one-time host resources (no device memory)
    static cudaStream_t s2 = nullptr;
    static cudaEvent_t evFork = nullptr, evJoin = nullptr;
    if (!s2) {
        cudaStreamCreateWithFlags(&s2, cudaStreamNonBlocking);
        cudaEventCreateWithFlags(&evFork, cudaEventDisableTiming);
        cudaEventCreateWithFlags(&evJoin, cudaEventDisableTiming);
    }

    const int T = 256;
    const int nb = (n + 255) / 256;
    int gemmGrid   = (n + 63) / 64;
    int gatherGrid = (n * 16 + T - 1) / T;

    // fork: CSR build on s2, GEMM1 on default stream, concurrently
    cudaEventRecord(evFork, 0);
    cudaStreamWaitEvent(s2, evFork, 0);

    // s2: CSR build
    cudaMemsetAsync(cnt, 0, (size_t)n * sizeof(int), s2);
    k_count<<<(E + T - 1) / T, T, 0, s2>>>(ei, E, cnt);
    k_scan_local<<<nb, 256, 0, s2>>>(cnt, n, off, bsum);
    k_scan_block<<<1, 512, 0, s2>>>(bsum, nb, bbase);
    k_scan_add<<<(n + T - 1) / T, T, 0, s2>>>(cnt, n, off, bbase, cur, dinv);
    k_fill<<<(E + T - 1) / T, T, 0, s2>>>(ei, E, dinv, cur, csr);
    cudaEventRecord(evJoin, s2);

    // default stream: layer-1 GEMM (independent of CSR build)
    k_gemm<128, false><<<gemmGrid, T>>>(x, W1, h, n);
    // zero pooled/cntf early (independent)
    cudaMemsetAsync(pooled, 0, N_GRAPHS * HID * sizeof(float), 0);
    cudaMemsetAsync(cntf, 0, N_GRAPHS * sizeof(float), 0);

    // join
    cudaStreamWaitEvent(0, evJoin, 0);

    // layer 1 gather
    k_gather<<<gatherGrid, T>>>(off, csr, dinv, h, b1, agg, n);
    // layer 2
    k_gemm<64, true><<<gemmGrid, T>>>(agg, W2, h, n);
    k_gather<<<gatherGrid, T>>>(off, csr, dinv, h, b2, agg, n);
    // layer 3
    k_gemm<64, true><<<gemmGrid, T>>>(agg, W3, h, n);
    k_gather<<<gatherGrid, T>>>(off, csr, dinv, h, b3, agg, n);

    // pooling + head
    k_pool<<<(n + POOL_NODES - 1) / POOL_NODES, T>>>(agg, batch, n, pooled, cntf);
    k_final<<<1, 128>>>(pooled, cntf, Wlin, blin, out);
}